// round 6
// baseline (speedup 1.0000x reference)
#include <cuda_runtime.h>
#include <cuda_fp16.h>
#include <math.h>
#include <stdint.h>

#define E_TOT 480000
#define N_TOT 30000
#define SCAT_B 1184
#define EB 7500
#define NB 469
#define GRID_TOT (SCAT_B + EB + NB)   // 9153

constexpr int SA_H = 264;  // A row stride (halves)
constexpr int SW_H = 72;   // W tile row stride (halves)

// smem (bytes): A 64x264x2=33792 | Wb 2x256x72x2=73728 | S4 2048 | WrS 3072
#define B_A    0
#define B_WB   33792
#define B_S4   107520
#define B_WR   109568
#define SMEM_BYTES 112640

__device__ float g_agg[(size_t)N_TOT * 128];
__device__ unsigned g_scatter_done;
#define EOFF 0
#define NOFF 229888
__device__ __align__(16) __half g_wh[483584];

// ---------------- helpers ----------------
__device__ __forceinline__ uint32_t smem_u32(const void* p) {
    uint32_t a;
    asm("{ .reg .u64 t; cvta.to.shared.u64 t, %1; cvt.u32.u64 %0, t; }" : "=r"(a) : "l"(p));
    return a;
}
__device__ __forceinline__ void cpa16(uint32_t s, const void* g) {
    asm volatile("cp.async.cg.shared.global [%0], [%1], 16;" :: "r"(s), "l"(g));
}
#define LDSM_X4(r0, r1, r2, r3, a) \
    asm volatile("ldmatrix.sync.aligned.m8n8.x4.shared.b16 {%0,%1,%2,%3}, [%4];" \
        : "=r"(r0), "=r"(r1), "=r"(r2), "=r"(r3) : "r"(a))
#define LDSM_X2(r0, r1, a) \
    asm volatile("ldmatrix.sync.aligned.m8n8.x2.shared.b16 {%0,%1}, [%2];" \
        : "=r"(r0), "=r"(r1) : "r"(a))
__device__ __forceinline__ void mma16(float* c, const uint32_t a[4], uint32_t b0, uint32_t b1) {
    asm volatile("mma.sync.aligned.m16n8k16.row.col.f32.f16.f16.f32 "
        "{%0,%1,%2,%3},{%4,%5,%6,%7},{%8,%9},{%0,%1,%2,%3};"
        : "+f"(c[0]), "+f"(c[1]), "+f"(c[2]), "+f"(c[3])
        : "r"(a[0]), "r"(a[1]), "r"(a[2]), "r"(a[3]), "r"(b0), "r"(b1));
}

// issue tile-0 prefetch for a layer into slot 0 (slot 0 is always free after a GEMM: NT even)
template<int K, int WR>
__device__ __forceinline__ void prefetch0(const __half* __restrict__ Wg, int wrows,
                                          __half* Wb, int tid)
{
    for (int idx = tid; idx < WR * 8; idx += 256) {
        int n = idx >> 3, q = idx & 7;
        if (n < wrows)
            cpa16(smem_u32(Wb + n * SW_H + q * 8), Wg + (size_t)n * K + q * 8);
    }
    asm volatile("cp.async.commit_group;");
}

// GEMM: C[64, 8*NTW*4] += A[64,K](fp16 smem) @ W[wrows,K]^T  (warps 2M x 4N)
// Tile-0 prefetch assumed already issued (prefetch0).
template<int K, int WR, int NTW>
__device__ __forceinline__ void gemm16(
    const __half* __restrict__ Wg, int wrows,
    const __half* As, __half* Wb, float* c,
    int tid, int lane, int wm, int wn)
{
    constexpr int NT = K / 64;
    int mq = lane >> 3, lr = lane & 7;

    for (int kt = 0; kt < NT; kt++) {
        const __half* cur = Wb + (kt & 1) * (WR * SW_H);
        if (kt + 1 < NT) {
            __half* nxt = Wb + ((kt + 1) & 1) * (WR * SW_H);
            for (int idx = tid; idx < WR * 8; idx += 256) {
                int n = idx >> 3, q = idx & 7;
                if (n < wrows)
                    cpa16(smem_u32(nxt + n * SW_H + q * 8),
                          Wg + (size_t)n * K + (kt + 1) * 64 + q * 8);
            }
            asm volatile("cp.async.commit_group;");
            asm volatile("cp.async.wait_group 1;");
        } else {
            asm volatile("cp.async.wait_group 0;");
        }
        __syncthreads();
#pragma unroll
        for (int ks = 0; ks < 4; ks++) {
            uint32_t a0[4], a1[4];
            uint32_t aad0 = smem_u32(As + (32 * wm + (mq & 1) * 8 + lr) * SA_H
                                        + kt * 64 + ks * 16 + (mq >> 1) * 8);
            LDSM_X4(a0[0], a0[1], a0[2], a0[3], aad0);
            LDSM_X4(a1[0], a1[1], a1[2], a1[3], aad0 + 16 * SA_H * 2);
#pragma unroll
            for (int p = 0; p < NTW / 2; p++) {
                uint32_t b0, b1, b2, b3;
                uint32_t bad = smem_u32(cur + (wn * (NTW * 8) + p * 16 + (mq >> 1) * 8 + lr) * SW_H
                                            + ks * 16 + (mq & 1) * 8);
                LDSM_X4(b0, b1, b2, b3, bad);
                mma16(c + (0 * NTW + 2 * p) * 4,     a0, b0, b1);
                mma16(c + (1 * NTW + 2 * p) * 4,     a1, b0, b1);
                mma16(c + (0 * NTW + 2 * p + 1) * 4, a0, b2, b3);
                mma16(c + (1 * NTW + 2 * p + 1) * 4, a1, b2, b3);
            }
            if (NTW & 1) {
                int i = lane & 15;
                uint32_t b0, b1;
                uint32_t bad = smem_u32(cur + (wn * (NTW * 8) + (NTW - 1) * 8 + (i & 7)) * SW_H
                                            + ks * 16 + (i >> 3) * 8);
                LDSM_X2(b0, b1, bad);
                mma16(c + (0 * NTW + NTW - 1) * 4, a0, b0, b1);
                mma16(c + (1 * NTW + NTW - 1) * 4, a1, b0, b1);
            }
        }
        __syncthreads();
    }
}

// ---------------- fused MLP body (64-row tile) ----------------
template<int MODE, int WRF, int NTWF, int NVF>
__device__ __forceinline__ void mlp_body(
    int row0,
    const float* __restrict__ m, const float* __restrict__ rbf, const float* __restrict__ Wr,
    const float* __restrict__ lng, const float* __restrict__ lnb,
    const float* __restrict__ bd,
    const __half* __restrict__ Wup, const __half* __restrict__ Wd, const __half* __restrict__ Wf,
    float* __restrict__ out, int nrows, unsigned char* smraw)
{
    __half* A   = reinterpret_cast<__half*>(smraw + B_A);
    __half* Wb  = reinterpret_cast<__half*>(smraw + B_WB);
    float*  S4  = reinterpret_cast<float*>(smraw + B_S4);
    float*  WrS = reinterpret_cast<float*>(smraw + B_WR);

    int tid = threadIdx.x, wid = tid >> 5, lane = tid & 31;
    int wm = wid & 1, wn = wid >> 1, g = lane >> 2, t = lane & 3;

    // prefetch L0 tile-0 while we do stage0
    prefetch0<128, 256>(Wup, 256, Wb, tid);

    // ---- stage0: A[64, 0:128] fp16 ----
    {
        int r = tid >> 2, kh = (tid & 3) * 32;
        if (MODE == 0) {
            for (int i = tid; i < 768; i += 256) WrS[i] = Wr[i];
            __syncthreads();
            const float* rb = rbf + (size_t)(row0 + r) * 6;
            float b0 = rb[0], b1 = rb[1], b2 = rb[2], b3 = rb[3], b4 = rb[4], b5 = rb[5];
            const float* mr = m + (size_t)(row0 + r) * 128;
            for (int k0 = kh; k0 < kh + 32; k0 += 4) {
                float4 mv = *reinterpret_cast<const float4*>(mr + k0);
                float cf[4];
#pragma unroll
                for (int j = 0; j < 4; j++) {
                    const float* w = WrS + (k0 + j) * 6;
                    cf[j] = b0*w[0] + b1*w[1] + b2*w[2] + b3*w[3] + b4*w[4] + b5*w[5];
                }
                *reinterpret_cast<__half2*>(A + r * SA_H + k0)     = __floats2half2_rn(mv.x * cf[0], mv.y * cf[1]);
                *reinterpret_cast<__half2*>(A + r * SA_H + k0 + 2) = __floats2half2_rn(mv.z * cf[2], mv.w * cf[3]);
            }
        } else {
            bool valid = (row0 + r) < nrows;
            const float* srcp = g_agg + (size_t)(row0 + r) * 128;
            for (int k0 = kh; k0 < kh + 32; k0 += 4) {
                float4 v = valid ? *reinterpret_cast<const float4*>(srcp + k0)
                                 : make_float4(0.f, 0.f, 0.f, 0.f);
                *reinterpret_cast<__half2*>(A + r * SA_H + k0)     = __floats2half2_rn(v.x, v.y);
                *reinterpret_cast<__half2*>(A + r * SA_H + k0 + 2) = __floats2half2_rn(v.z, v.w);
            }
        }
    }
    __syncthreads();

    float c[64];

    // ---- L0: up (K=128) + LayerNorm ----
#pragma unroll
    for (int i = 0; i < 64; i++) c[i] = 0.f;
    gemm16<128, 256, 8>(Wup, 256, A, Wb, c, tid, lane, wm, wn);
    prefetch0<256, 256>(Wd, 256, Wb, tid);   // L1 tile-0 hides under LN epilogue
    {
        float s[4] = {0.f, 0.f, 0.f, 0.f}, q2[4] = {0.f, 0.f, 0.f, 0.f};
#pragma unroll
        for (int mt = 0; mt < 2; mt++)
#pragma unroll
            for (int nt = 0; nt < 8; nt++) {
                const float* cc = c + (mt * 8 + nt) * 4;
                s[mt*2]   += cc[0] + cc[1]; q2[mt*2]   += cc[0]*cc[0] + cc[1]*cc[1];
                s[mt*2+1] += cc[2] + cc[3]; q2[mt*2+1] += cc[2]*cc[2] + cc[3]*cc[3];
            }
#pragma unroll
        for (int off = 1; off <= 2; off <<= 1)
#pragma unroll
            for (int i = 0; i < 4; i++) {
                s[i]  += __shfl_xor_sync(0xffffffffu, s[i],  off);
                q2[i] += __shfl_xor_sync(0xffffffffu, q2[i], off);
            }
        if (t == 0) {
#pragma unroll
            for (int i = 0; i < 4; i++) {
                int row = 32 * wm + 16 * (i >> 1) + g + 8 * (i & 1);
                S4[row * 8 + wn]     = s[i];
                S4[row * 8 + 4 + wn] = q2[i];
            }
        }
        __syncthreads();
        float mu[4], rs[4];
#pragma unroll
        for (int i = 0; i < 4; i++) {
            int row = 32 * wm + 16 * (i >> 1) + g + 8 * (i & 1);
            float sum = S4[row*8+0] + S4[row*8+1] + S4[row*8+2] + S4[row*8+3];
            float sq  = S4[row*8+4] + S4[row*8+5] + S4[row*8+6] + S4[row*8+7];
            float m_ = sum * (1.f / 256.f);
            mu[i] = m_;
            rs[i] = rsqrtf(sq * (1.f / 256.f) - m_ * m_ + 1e-5f);
        }
#pragma unroll
        for (int mt = 0; mt < 2; mt++) {
            int rA = 32 * wm + 16 * mt + g, rB = rA + 8;
            int iA = mt * 2, iB = mt * 2 + 1;
#pragma unroll
            for (int nt = 0; nt < 8; nt++) {
                int col = 64 * wn + 8 * nt + 2 * t;
                const float* cc = c + (mt * 8 + nt) * 4;
                float g0 = __ldg(lng + col), g1 = __ldg(lng + col + 1);
                float e0 = __ldg(lnb + col), e1 = __ldg(lnb + col + 1);
                *reinterpret_cast<__half2*>(A + rA * SA_H + col) =
                    __floats2half2_rn((cc[0] - mu[iA]) * rs[iA] * g0 + e0,
                                      (cc[1] - mu[iA]) * rs[iA] * g1 + e1);
                *reinterpret_cast<__half2*>(A + rB * SA_H + col) =
                    __floats2half2_rn((cc[2] - mu[iB]) * rs[iB] * g0 + e0,
                                      (cc[3] - mu[iB]) * rs[iB] * g1 + e1);
            }
        }
    }

    // ---- L1..L3 dense + SiLU ----
    for (int L = 0; L < 3; L++) {
#pragma unroll
        for (int i = 0; i < 64; i++) c[i] = 0.f;
        gemm16<256, 256, 8>(Wd + L * 65536, 256, A, Wb, c, tid, lane, wm, wn);
        // prefetch next layer's tile-0 so the epilogue hides it
        if (L < 2)            prefetch0<256, 256>(Wd + (L + 1) * 65536, 256, Wb, tid);
        else if (MODE == 1)   prefetch0<256, 96>(Wf, NVF, Wb, tid);
        const float* bias = bd + L * 256;
#pragma unroll
        for (int mt = 0; mt < 2; mt++) {
            int rA = 32 * wm + 16 * mt + g, rB = rA + 8;
#pragma unroll
            for (int nt = 0; nt < 8; nt++) {
                int col = 64 * wn + 8 * nt + 2 * t;
                const float* cc = c + (mt * 8 + nt) * 4;
                float b0 = __ldg(bias + col), b1 = __ldg(bias + col + 1);
                float v0 = cc[0] + b0; v0 = v0 / (1.f + __expf(-v0));
                float v1 = cc[1] + b1; v1 = v1 / (1.f + __expf(-v1));
                float v2 = cc[2] + b0; v2 = v2 / (1.f + __expf(-v2));
                float v3 = cc[3] + b1; v3 = v3 / (1.f + __expf(-v3));
                *reinterpret_cast<__half2*>(A + rA * SA_H + col) = __floats2half2_rn(v0, v1);
                *reinterpret_cast<__half2*>(A + rB * SA_H + col) = __floats2half2_rn(v2, v3);
            }
        }
        __syncthreads();
    }

    if (MODE == 0) {
        // ---- edge final: 256->2 on CUDA cores (no barriers, no GEMM) ----
        if (tid < 128) {
            int r = tid >> 1, o = tid & 1;
            const __half2* arow = reinterpret_cast<const __half2*>(A + r * SA_H);
            const __half2* wrow = reinterpret_cast<const __half2*>(Wf + o * 256);
            float acc = 0.f;
#pragma unroll 16
            for (int k = 0; k < 128; k++) {
                float2 a = __half22float2(arow[k]);
                float2 w = __half22float2(__ldg(&wrow[k]));
                acc = fmaf(a.x, w.x, acc);
                acc = fmaf(a.y, w.y, acc);
            }
            out[(size_t)(row0 + r) * 2 + o] = acc;
        }
    } else {
        // ---- node final: 256->95 GEMM (padded to 96) ----
#pragma unroll
        for (int i = 0; i < 2 * NTWF * 4; i++) c[i] = 0.f;
        gemm16<256, WRF, NTWF>(Wf, NVF, A, Wb, c, tid, lane, wm, wn);
#pragma unroll
        for (int mt = 0; mt < 2; mt++) {
            int rA = row0 + 32 * wm + 16 * mt + g, rB = rA + 8;
#pragma unroll
            for (int nt = 0; nt < NTWF; nt++) {
                int col = wn * (NTWF * 8) + nt * 8 + 2 * t;
                const float* cc = c + (mt * NTWF + nt) * 4;
                if (rA < nrows) {
                    if (col < 95)     out[(size_t)rA * 95 + col]     = cc[0];
                    if (col + 1 < 95) out[(size_t)rA * 95 + col + 1] = cc[1];
                }
                if (rB < nrows) {
                    if (col < 95)     out[(size_t)rB * 95 + col]     = cc[2];
                    if (col + 1 < 95) out[(size_t)rB * 95 + col + 1] = cc[3];
                }
            }
        }
    }
}

// ---------------- scatter body (runs inside mega kernel) ----------------
__device__ __forceinline__ void scatter_body(
    int sid,
    const float* __restrict__ m, const float* __restrict__ rbf,
    const int* __restrict__ src, const float* __restrict__ Wr,
    unsigned char* smraw)
{
    float* Wrs = reinterpret_cast<float*>(smraw);
    for (int idx = threadIdx.x; idx < 128 * 6; idx += 256) Wrs[idx] = Wr[idx];
    __syncthreads();
    int sub = threadIdx.x >> 7;
    int k   = threadIdx.x & 127;
    for (long long e = (long long)sid * 2 + sub; e < E_TOT; e += (long long)SCAT_B * 2) {
        const float* rb = rbf + e * 6;
        float r0 = __ldg(rb+0), r1 = __ldg(rb+1), r2 = __ldg(rb+2);
        float r3 = __ldg(rb+3), r4 = __ldg(rb+4), r5 = __ldg(rb+5);
        const float* wr = Wrs + k * 6;
        float cc = r0*wr[0] + r1*wr[1] + r2*wr[2] + r3*wr[3] + r4*wr[4] + r5*wr[5];
        float v = m[(size_t)e * 128 + k] * cc;
        int s = __ldg(src + e);
        atomicAdd(g_agg + (size_t)s * 128 + k, v);
    }
    __syncthreads();
    __threadfence();
    if (threadIdx.x == 0) atomicAdd(&g_scatter_done, 1u);
}

// ---------------- mega kernel: scatter (interleaved) + edge + node ----------------
__global__ void __launch_bounds__(256, 2) mega(
    const float* __restrict__ m, const float* __restrict__ rbf, const int* __restrict__ src,
    const float* __restrict__ Wr_e, const float* __restrict__ Wr_n,
    const float* __restrict__ lng_e, const float* __restrict__ lnb_e, const float* __restrict__ bd_e,
    const float* __restrict__ lng_n, const float* __restrict__ lnb_n, const float* __restrict__ bd_n,
    float* __restrict__ edge_out, float* __restrict__ node_out)
{
    extern __shared__ unsigned char smraw[];
    int bx = blockIdx.x;

    // first 4736 blocks: groups of 4 = {3 edge, 1 scatter}
    if (bx < 4 * SCAT_B) {
        int j = bx >> 2, r = bx & 3;
        if (r == 3) {
            scatter_body(j, m, rbf, src, Wr_n, smraw);
            return;
        }
        int eid = 3 * j + r;
        mlp_body<0, 8, 1, 2>(eid * 64, m, rbf, Wr_e, lng_e, lnb_e, bd_e,
                             g_wh + EOFF, g_wh + EOFF + 32768, g_wh + EOFF + 229376,
                             edge_out, E_TOT, smraw);
        return;
    }
    int rest = bx - 4 * SCAT_B;
    if (rest < EB - 3 * SCAT_B) {
        int eid = 3 * SCAT_B + rest;
        mlp_body<0, 8, 1, 2>(eid * 64, m, rbf, Wr_e, lng_e, lnb_e, bd_e,
                             g_wh + EOFF, g_wh + EOFF + 32768, g_wh + EOFF + 229376,
                             edge_out, E_TOT, smraw);
        return;
    }
    // node blocks: wait for all scatter blocks
    int nid = rest - (EB - 3 * SCAT_B);
    if (threadIdx.x == 0) {
        while (atomicAdd(&g_scatter_done, 0u) < SCAT_B) __nanosleep(64);
    }
    __syncthreads();
    __threadfence();
    mlp_body<1, 96, 3, 95>(nid * 64, nullptr, nullptr, nullptr,
                           lng_n, lnb_n, bd_n,
                           g_wh + NOFF, g_wh + NOFF + 32768, g_wh + NOFF + 229376,
                           node_out, N_TOT, smraw);
}

// ---------------- prep kernels ----------------
__global__ void cvt_branch(const float* __restrict__ up, const float* __restrict__ wd,
                           const float* __restrict__ fin, int fin_n, int base)
{
    int i = blockIdx.x * 256 + threadIdx.x;
    if (i < 32768)                 g_wh[base + i] = __float2half_rn(up[i]);
    else if (i < 229376)           g_wh[base + i] = __float2half_rn(wd[i - 32768]);
    else if (i < 229376 + fin_n)   g_wh[base + i] = __float2half_rn(fin[i - 229376]);
}

__global__ void zero_agg_kernel()
{
    if (blockIdx.x == 0 && threadIdx.x == 0) g_scatter_done = 0u;
    size_t n = (size_t)N_TOT * 128;
    for (size_t i = (size_t)blockIdx.x * blockDim.x + threadIdx.x; i < n;
         i += (size_t)gridDim.x * blockDim.x)
        g_agg[i] = 0.f;
}

// ---------------- launch ----------------
extern "C" void kernel_launch(void* const* d_in, const int* in_sizes, int n_in,
                              void* d_out, int out_size)
{
    const float* m       = (const float*)d_in[0];
    const float* rbf     = (const float*)d_in[1];
    const int*   src     = (const int*)  d_in[2];
    const float* W_rbf_e = (const float*)d_in[3];
    const float* W_up_e  = (const float*)d_in[4];
    const float* ln_g_e  = (const float*)d_in[5];
    const float* ln_b_e  = (const float*)d_in[6];
    const float* Wd_e    = (const float*)d_in[7];
    const float* bd_e    = (const float*)d_in[8];
    const float* W_fin_e = (const float*)d_in[9];
    const float* W_rbf_n = (const float*)d_in[10];
    const float* W_up_n  = (const float*)d_in[11];
    const float* ln_g_n  = (const float*)d_in[12];
    const float* ln_b_n  = (const float*)d_in[13];
    const float* Wd_n    = (const float*)d_in[14];
    const float* bd_n    = (const float*)d_in[15];
    const float* W_fin_n = (const float*)d_in[16];

    float* edge_out = (float*)d_out;
    float* node_out = (float*)d_out + (size_t)E_TOT * 2;

    cudaFuncSetAttribute((const void*)mega,
                         cudaFuncAttributeMaxDynamicSharedMemorySize, SMEM_BYTES);

    cvt_branch<<<(229888 + 255) / 256, 256>>>(W_up_e, Wd_e, W_fin_e, 512,   EOFF);   // 0
    cvt_branch<<<(253696 + 255) / 256, 256>>>(W_up_n, Wd_n, W_fin_n, 24320, NOFF);   // 1
    zero_agg_kernel<<<512, 256>>>();                                                  // 2
    mega<<<GRID_TOT, 256, SMEM_BYTES>>>(                                              // 3
        m, rbf, src, W_rbf_e, W_rbf_n,
        ln_g_e, ln_b_e, bd_e, ln_g_n, ln_b_n, bd_n,
        edge_out, node_out);
}

// round 7
// speedup vs baseline: 1.0190x; 1.0190x over previous
#include <cuda_runtime.h>
#include <cuda_fp16.h>
#include <math.h>
#include <stdint.h>

#define E_TOT 480000
#define N_TOT 30000
#define EB 7500   // edge blocks (64 rows each)
#define NB 469    // node blocks

constexpr int SA_H = 264;  // A row stride (halves)
constexpr int SW_H = 72;   // W tile row stride (halves)

// smem (bytes): A 64x264x2=33792 | Wb 2x256x72x2=73728 | S4 2048 | WrS 3072
#define B_A    0
#define B_WB   33792
#define B_S4   107520
#define B_WR   109568
#define SMEM_BYTES 112640

__device__ float g_agg[(size_t)N_TOT * 128];
#define EOFF 0
#define NOFF 229888
__device__ __align__(16) __half g_wh[483584];

// ---------------- helpers ----------------
__device__ __forceinline__ uint32_t smem_u32(const void* p) {
    uint32_t a;
    asm("{ .reg .u64 t; cvta.to.shared.u64 t, %1; cvt.u32.u64 %0, t; }" : "=r"(a) : "l"(p));
    return a;
}
__device__ __forceinline__ void cpa16(uint32_t s, const void* g) {
    asm volatile("cp.async.cg.shared.global [%0], [%1], 16;" :: "r"(s), "l"(g));
}
#define LDSM_X4(r0, r1, r2, r3, a) \
    asm volatile("ldmatrix.sync.aligned.m8n8.x4.shared.b16 {%0,%1,%2,%3}, [%4];" \
        : "=r"(r0), "=r"(r1), "=r"(r2), "=r"(r3) : "r"(a))
#define LDSM_X2(r0, r1, a) \
    asm volatile("ldmatrix.sync.aligned.m8n8.x2.shared.b16 {%0,%1}, [%2];" \
        : "=r"(r0), "=r"(r1) : "r"(a))
__device__ __forceinline__ void mma16(float* c, const uint32_t a[4], uint32_t b0, uint32_t b1) {
    asm volatile("mma.sync.aligned.m16n8k16.row.col.f32.f16.f16.f32 "
        "{%0,%1,%2,%3},{%4,%5,%6,%7},{%8,%9},{%0,%1,%2,%3};"
        : "+f"(c[0]), "+f"(c[1]), "+f"(c[2]), "+f"(c[3])
        : "r"(a[0]), "r"(a[1]), "r"(a[2]), "r"(a[3]), "r"(b0), "r"(b1));
}

// issue tile-0 prefetch for a layer into slot 0 (slot 0 free after any GEMM: NT even)
template<int K, int WR>
__device__ __forceinline__ void prefetch0(const __half* __restrict__ Wg, int wrows,
                                          __half* Wb, int tid)
{
    for (int idx = tid; idx < WR * 8; idx += 256) {
        int n = idx >> 3, q = idx & 7;
        if (n < wrows)
            cpa16(smem_u32(Wb + n * SW_H + q * 8), Wg + (size_t)n * K + q * 8);
    }
    asm volatile("cp.async.commit_group;");
}

// GEMM: C[64, 8*NTW*4] += A[64,K](fp16 smem) @ W[wrows,K]^T  (warps 2M x 4N)
// Tile-0 prefetch assumed already issued.
template<int K, int WR, int NTW>
__device__ __forceinline__ void gemm16(
    const __half* __restrict__ Wg, int wrows,
    const __half* As, __half* Wb, float* c,
    int tid, int lane, int wm, int wn)
{
    constexpr int NT = K / 64;
    int mq = lane >> 3, lr = lane & 7;

    for (int kt = 0; kt < NT; kt++) {
        const __half* cur = Wb + (kt & 1) * (WR * SW_H);
        if (kt + 1 < NT) {
            __half* nxt = Wb + ((kt + 1) & 1) * (WR * SW_H);
            for (int idx = tid; idx < WR * 8; idx += 256) {
                int n = idx >> 3, q = idx & 7;
                if (n < wrows)
                    cpa16(smem_u32(nxt + n * SW_H + q * 8),
                          Wg + (size_t)n * K + (kt + 1) * 64 + q * 8);
            }
            asm volatile("cp.async.commit_group;");
            asm volatile("cp.async.wait_group 1;");
        } else {
            asm volatile("cp.async.wait_group 0;");
        }
        __syncthreads();
#pragma unroll
        for (int ks = 0; ks < 4; ks++) {
            uint32_t a0[4], a1[4];
            uint32_t aad0 = smem_u32(As + (32 * wm + (mq & 1) * 8 + lr) * SA_H
                                        + kt * 64 + ks * 16 + (mq >> 1) * 8);
            LDSM_X4(a0[0], a0[1], a0[2], a0[3], aad0);
            LDSM_X4(a1[0], a1[1], a1[2], a1[3], aad0 + 16 * SA_H * 2);
#pragma unroll
            for (int p = 0; p < NTW / 2; p++) {
                uint32_t b0, b1, b2, b3;
                uint32_t bad = smem_u32(cur + (wn * (NTW * 8) + p * 16 + (mq >> 1) * 8 + lr) * SW_H
                                            + ks * 16 + (mq & 1) * 8);
                LDSM_X4(b0, b1, b2, b3, bad);
                mma16(c + (0 * NTW + 2 * p) * 4,     a0, b0, b1);
                mma16(c + (1 * NTW + 2 * p) * 4,     a1, b0, b1);
                mma16(c + (0 * NTW + 2 * p + 1) * 4, a0, b2, b3);
                mma16(c + (1 * NTW + 2 * p + 1) * 4, a1, b2, b3);
            }
            if (NTW & 1) {
                int i = lane & 15;
                uint32_t b0, b1;
                uint32_t bad = smem_u32(cur + (wn * (NTW * 8) + (NTW - 1) * 8 + (i & 7)) * SW_H
                                            + ks * 16 + (i >> 3) * 8);
                LDSM_X2(b0, b1, bad);
                mma16(c + (0 * NTW + NTW - 1) * 4, a0, b0, b1);
                mma16(c + (1 * NTW + NTW - 1) * 4, a1, b0, b1);
            }
        }
        __syncthreads();
    }
}

// ---------------- fused MLP body (64-row tile) ----------------
template<int MODE, int WRF, int NTWF, int NVF>
__device__ __forceinline__ void mlp_body(
    int row0,
    const float* __restrict__ m, const float* __restrict__ rbf, const float* __restrict__ Wr,
    const float* __restrict__ lng, const float* __restrict__ lnb,
    const float* __restrict__ bd,
    const __half* __restrict__ Wup, const __half* __restrict__ Wd, const __half* __restrict__ Wf,
    float* __restrict__ out, int nrows, unsigned char* smraw)
{
    __half* A   = reinterpret_cast<__half*>(smraw + B_A);
    __half* Wb  = reinterpret_cast<__half*>(smraw + B_WB);
    float*  S4  = reinterpret_cast<float*>(smraw + B_S4);
    float*  WrS = reinterpret_cast<float*>(smraw + B_WR);

    int tid = threadIdx.x, wid = tid >> 5, lane = tid & 31;
    int wm = wid & 1, wn = wid >> 1, g = lane >> 2, t = lane & 3;

    // prefetch L0 tile-0 while we do stage0
    prefetch0<128, 256>(Wup, 256, Wb, tid);

    // ---- stage0: A[64, 0:128] fp16 ----
    {
        int r = tid >> 2, kh = (tid & 3) * 32;
        if (MODE == 0) {
            for (int i = tid; i < 768; i += 256) WrS[i] = Wr[i];
            __syncthreads();
            const float* rb = rbf + (size_t)(row0 + r) * 6;
            float b0 = rb[0], b1 = rb[1], b2 = rb[2], b3 = rb[3], b4 = rb[4], b5 = rb[5];
            const float* mr = m + (size_t)(row0 + r) * 128;
            for (int k0 = kh; k0 < kh + 32; k0 += 4) {
                float4 mv = *reinterpret_cast<const float4*>(mr + k0);
                float cf[4];
#pragma unroll
                for (int j = 0; j < 4; j++) {
                    const float* w = WrS + (k0 + j) * 6;
                    cf[j] = b0*w[0] + b1*w[1] + b2*w[2] + b3*w[3] + b4*w[4] + b5*w[5];
                }
                *reinterpret_cast<__half2*>(A + r * SA_H + k0)     = __floats2half2_rn(mv.x * cf[0], mv.y * cf[1]);
                *reinterpret_cast<__half2*>(A + r * SA_H + k0 + 2) = __floats2half2_rn(mv.z * cf[2], mv.w * cf[3]);
            }
        } else {
            bool valid = (row0 + r) < nrows;
            const float* srcp = g_agg + (size_t)(row0 + r) * 128;
            for (int k0 = kh; k0 < kh + 32; k0 += 4) {
                float4 v = valid ? *reinterpret_cast<const float4*>(srcp + k0)
                                 : make_float4(0.f, 0.f, 0.f, 0.f);
                *reinterpret_cast<__half2*>(A + r * SA_H + k0)     = __floats2half2_rn(v.x, v.y);
                *reinterpret_cast<__half2*>(A + r * SA_H + k0 + 2) = __floats2half2_rn(v.z, v.w);
            }
        }
    }
    __syncthreads();

    float c[64];

    // ---- L0: up (K=128) + LayerNorm ----
#pragma unroll
    for (int i = 0; i < 64; i++) c[i] = 0.f;
    gemm16<128, 256, 8>(Wup, 256, A, Wb, c, tid, lane, wm, wn);
    prefetch0<256, 256>(Wd, 256, Wb, tid);   // L1 tile-0 hides under LN epilogue
    {
        float s[4] = {0.f, 0.f, 0.f, 0.f}, q2[4] = {0.f, 0.f, 0.f, 0.f};
#pragma unroll
        for (int mt = 0; mt < 2; mt++)
#pragma unroll
            for (int nt = 0; nt < 8; nt++) {
                const float* cc = c + (mt * 8 + nt) * 4;
                s[mt*2]   += cc[0] + cc[1]; q2[mt*2]   += cc[0]*cc[0] + cc[1]*cc[1];
                s[mt*2+1] += cc[2] + cc[3]; q2[mt*2+1] += cc[2]*cc[2] + cc[3]*cc[3];
            }
#pragma unroll
        for (int off = 1; off <= 2; off <<= 1)
#pragma unroll
            for (int i = 0; i < 4; i++) {
                s[i]  += __shfl_xor_sync(0xffffffffu, s[i],  off);
                q2[i] += __shfl_xor_sync(0xffffffffu, q2[i], off);
            }
        if (t == 0) {
#pragma unroll
            for (int i = 0; i < 4; i++) {
                int row = 32 * wm + 16 * (i >> 1) + g + 8 * (i & 1);
                S4[row * 8 + wn]     = s[i];
                S4[row * 8 + 4 + wn] = q2[i];
            }
        }
        __syncthreads();
        float mu[4], rs[4];
#pragma unroll
        for (int i = 0; i < 4; i++) {
            int row = 32 * wm + 16 * (i >> 1) + g + 8 * (i & 1);
            float sum = S4[row*8+0] + S4[row*8+1] + S4[row*8+2] + S4[row*8+3];
            float sq  = S4[row*8+4] + S4[row*8+5] + S4[row*8+6] + S4[row*8+7];
            float m_ = sum * (1.f / 256.f);
            mu[i] = m_;
            rs[i] = rsqrtf(sq * (1.f / 256.f) - m_ * m_ + 1e-5f);
        }
#pragma unroll
        for (int mt = 0; mt < 2; mt++) {
            int rA = 32 * wm + 16 * mt + g, rB = rA + 8;
            int iA = mt * 2, iB = mt * 2 + 1;
#pragma unroll
            for (int nt = 0; nt < 8; nt++) {
                int col = 64 * wn + 8 * nt + 2 * t;
                const float* cc = c + (mt * 8 + nt) * 4;
                float g0 = __ldg(lng + col), g1 = __ldg(lng + col + 1);
                float e0 = __ldg(lnb + col), e1 = __ldg(lnb + col + 1);
                *reinterpret_cast<__half2*>(A + rA * SA_H + col) =
                    __floats2half2_rn((cc[0] - mu[iA]) * rs[iA] * g0 + e0,
                                      (cc[1] - mu[iA]) * rs[iA] * g1 + e1);
                *reinterpret_cast<__half2*>(A + rB * SA_H + col) =
                    __floats2half2_rn((cc[2] - mu[iB]) * rs[iB] * g0 + e0,
                                      (cc[3] - mu[iB]) * rs[iB] * g1 + e1);
            }
        }
    }

    // ---- L1..L3 dense + SiLU ----
    for (int L = 0; L < 3; L++) {
#pragma unroll
        for (int i = 0; i < 64; i++) c[i] = 0.f;
        gemm16<256, 256, 8>(Wd + L * 65536, 256, A, Wb, c, tid, lane, wm, wn);
        if (L < 2)            prefetch0<256, 256>(Wd + (L + 1) * 65536, 256, Wb, tid);
        else if (MODE == 1)   prefetch0<256, 96>(Wf, NVF, Wb, tid);
        const float* bias = bd + L * 256;
#pragma unroll
        for (int mt = 0; mt < 2; mt++) {
            int rA = 32 * wm + 16 * mt + g, rB = rA + 8;
#pragma unroll
            for (int nt = 0; nt < 8; nt++) {
                int col = 64 * wn + 8 * nt + 2 * t;
                const float* cc = c + (mt * 8 + nt) * 4;
                float b0 = __ldg(bias + col), b1 = __ldg(bias + col + 1);
                float v0 = cc[0] + b0; v0 = v0 / (1.f + __expf(-v0));
                float v1 = cc[1] + b1; v1 = v1 / (1.f + __expf(-v1));
                float v2 = cc[2] + b0; v2 = v2 / (1.f + __expf(-v2));
                float v3 = cc[3] + b1; v3 = v3 / (1.f + __expf(-v3));
                *reinterpret_cast<__half2*>(A + rA * SA_H + col) = __floats2half2_rn(v0, v1);
                *reinterpret_cast<__half2*>(A + rB * SA_H + col) = __floats2half2_rn(v2, v3);
            }
        }
        __syncthreads();
    }

    if (MODE == 0) {
        // ---- edge final: 256->2 on CUDA cores (no barriers) ----
        if (tid < 128) {
            int r = tid >> 1, o = tid & 1;
            const __half2* arow = reinterpret_cast<const __half2*>(A + r * SA_H);
            const __half2* wrow = reinterpret_cast<const __half2*>(Wf + o * 256);
            float acc = 0.f;
#pragma unroll 16
            for (int k = 0; k < 128; k++) {
                float2 a = __half22float2(arow[k]);
                float2 w = __half22float2(__ldg(&wrow[k]));
                acc = fmaf(a.x, w.x, acc);
                acc = fmaf(a.y, w.y, acc);
            }
            out[(size_t)(row0 + r) * 2 + o] = acc;
        }
    } else {
        // ---- node final: 256->95 GEMM (padded to 96) ----
#pragma unroll
        for (int i = 0; i < 2 * NTWF * 4; i++) c[i] = 0.f;
        gemm16<256, WRF, NTWF>(Wf, NVF, A, Wb, c, tid, lane, wm, wn);
#pragma unroll
        for (int mt = 0; mt < 2; mt++) {
            int rA = row0 + 32 * wm + 16 * mt + g, rB = rA + 8;
#pragma unroll
            for (int nt = 0; nt < NTWF; nt++) {
                int col = wn * (NTWF * 8) + nt * 8 + 2 * t;
                const float* cc = c + (mt * NTWF + nt) * 4;
                if (rA < nrows) {
                    if (col < 95)     out[(size_t)rA * 95 + col]     = cc[0];
                    if (col + 1 < 95) out[(size_t)rA * 95 + col + 1] = cc[1];
                }
                if (rB < nrows) {
                    if (col < 95)     out[(size_t)rB * 95 + col]     = cc[2];
                    if (col + 1 < 95) out[(size_t)rB * 95 + col + 1] = cc[3];
                }
            }
        }
    }
}

// ---------------- one fused launch: edge blocks then node blocks ----------------
__global__ void __launch_bounds__(256, 2) fused_all(
    const float* __restrict__ m, const float* __restrict__ rbf, const float* __restrict__ Wr_e,
    const float* __restrict__ lng_e, const float* __restrict__ lnb_e, const float* __restrict__ bd_e,
    const float* __restrict__ lng_n, const float* __restrict__ lnb_n, const float* __restrict__ bd_n,
    float* __restrict__ edge_out, float* __restrict__ node_out)
{
    extern __shared__ unsigned char smraw[];
    if (blockIdx.x < EB) {
        mlp_body<0, 8, 1, 2>(blockIdx.x * 64, m, rbf, Wr_e, lng_e, lnb_e, bd_e,
                             g_wh + EOFF, g_wh + EOFF + 32768, g_wh + EOFF + 229376,
                             edge_out, E_TOT, smraw);
    } else {
        mlp_body<1, 96, 3, 95>((blockIdx.x - EB) * 64, nullptr, nullptr, nullptr,
                               lng_n, lnb_n, bd_n,
                               g_wh + NOFF, g_wh + NOFF + 32768, g_wh + NOFF + 229376,
                               node_out, N_TOT, smraw);
    }
}

// ---------------- prep kernels ----------------
__global__ void cvt_branch(const float* __restrict__ up, const float* __restrict__ wd,
                           const float* __restrict__ fin, int fin_n, int base)
{
    int i = blockIdx.x * 256 + threadIdx.x;
    if (i < 32768)                 g_wh[base + i] = __float2half_rn(up[i]);
    else if (i < 229376)           g_wh[base + i] = __float2half_rn(wd[i - 32768]);
    else if (i < 229376 + fin_n)   g_wh[base + i] = __float2half_rn(fin[i - 229376]);
}

__global__ void zero_agg_kernel(int base)
{
    size_t n = (size_t)N_TOT * 64;
    for (size_t i = (size_t)blockIdx.x * blockDim.x + threadIdx.x; i < n;
         i += (size_t)gridDim.x * blockDim.x)
        g_agg[base + i] = 0.f;
}

// ---------------- scatter: red.global.add.v4.f32, 4 channels/thread ----------------
__global__ void __launch_bounds__(256) scatter_kernel(
    const float* __restrict__ m, const float* __restrict__ rbf,
    const int* __restrict__ src, const float* __restrict__ Wr)
{
    __shared__ float Wrs[128 * 6];
    for (int idx = threadIdx.x; idx < 128 * 6; idx += 256) Wrs[idx] = Wr[idx];
    __syncthreads();
    int sub  = threadIdx.x >> 5;        // 8 edges per block-iteration
    int lane = threadIdx.x & 31;
    int k4   = lane * 4;                // channel base
    const float* w0 = Wrs + (k4 + 0) * 6;
    const float* w1 = Wrs + (k4 + 1) * 6;
    const float* w2 = Wrs + (k4 + 2) * 6;
    const float* w3 = Wrs + (k4 + 3) * 6;
    for (long long e = (long long)blockIdx.x * 8 + sub; e < E_TOT;
         e += (long long)gridDim.x * 8) {
        const float* rb = rbf + e * 6;
        float r0 = __ldg(rb+0), r1 = __ldg(rb+1), r2 = __ldg(rb+2);
        float r3 = __ldg(rb+3), r4 = __ldg(rb+4), r5 = __ldg(rb+5);
        float c0 = r0*w0[0] + r1*w0[1] + r2*w0[2] + r3*w0[3] + r4*w0[4] + r5*w0[5];
        float c1 = r0*w1[0] + r1*w1[1] + r2*w1[2] + r3*w1[3] + r4*w1[4] + r5*w1[5];
        float c2 = r0*w2[0] + r1*w2[1] + r2*w2[2] + r3*w2[3] + r4*w2[4] + r5*w2[5];
        float c3 = r0*w3[0] + r1*w3[1] + r2*w3[2] + r3*w3[3] + r4*w3[4] + r5*w3[5];
        float4 mv = *reinterpret_cast<const float4*>(m + (size_t)e * 128 + k4);
        int s = __ldg(src + e);
        float* dst = g_agg + (size_t)s * 128 + k4;
        asm volatile("red.global.add.v4.f32 [%0], {%1, %2, %3, %4};"
                     :: "l"(dst), "f"(mv.x * c0), "f"(mv.y * c1),
                        "f"(mv.z * c2), "f"(mv.w * c3) : "memory");
    }
}

// ---------------- launch ----------------
extern "C" void kernel_launch(void* const* d_in, const int* in_sizes, int n_in,
                              void* d_out, int out_size)
{
    const float* m       = (const float*)d_in[0];
    const float* rbf     = (const float*)d_in[1];
    const int*   src     = (const int*)  d_in[2];
    const float* W_rbf_e = (const float*)d_in[3];
    const float* W_up_e  = (const float*)d_in[4];
    const float* ln_g_e  = (const float*)d_in[5];
    const float* ln_b_e  = (const float*)d_in[6];
    const float* Wd_e    = (const float*)d_in[7];
    const float* bd_e    = (const float*)d_in[8];
    const float* W_fin_e = (const float*)d_in[9];
    const float* W_rbf_n = (const float*)d_in[10];
    const float* W_up_n  = (const float*)d_in[11];
    const float* ln_g_n  = (const float*)d_in[12];
    const float* ln_b_n  = (const float*)d_in[13];
    const float* Wd_n    = (const float*)d_in[14];
    const float* bd_n    = (const float*)d_in[15];
    const float* W_fin_n = (const float*)d_in[16];

    float* edge_out = (float*)d_out;
    float* node_out = (float*)d_out + (size_t)E_TOT * 2;

    cudaFuncSetAttribute((const void*)fused_all,
                         cudaFuncAttributeMaxDynamicSharedMemorySize, SMEM_BYTES);

    // launch order: 0 cvt_e, 1 cvt_n, 2 zeroA, 3 zeroB, 4 scatter, 5 fused (ncu -s 5)
    cvt_branch<<<(229888 + 255) / 256, 256>>>(W_up_e, Wd_e, W_fin_e, 512,   EOFF);
    cvt_branch<<<(253696 + 255) / 256, 256>>>(W_up_n, Wd_n, W_fin_n, 24320, NOFF);
    zero_agg_kernel<<<256, 256>>>(0);
    zero_agg_kernel<<<256, 256>>>(N_TOT * 64);
    scatter_kernel<<<1184, 256>>>(m, rbf, src, W_rbf_n);
    fused_all<<<EB + NB, 256, SMEM_BYTES>>>(
        m, rbf, W_rbf_e, ln_g_e, ln_b_e, bd_e, ln_g_n, ln_b_n, bd_n,
        edge_out, node_out);
}

// round 8
// speedup vs baseline: 1.2457x; 1.2225x over previous
#include <cuda_runtime.h>
#include <cuda_fp16.h>
#include <math.h>
#include <stdint.h>

#define E_TOT 480000
#define N_TOT 30000
#define EB 7500   // edge blocks (64 rows each)
#define NB 469    // node blocks

constexpr int SA_H = 264;  // A row stride (halves)
constexpr int SW_H = 72;   // W tile row stride (halves)

// smem (bytes): A 64x264x2=33792 | Wb 2x256x72x2=73728 | S4 2048 | WrS 3072
#define B_A    0
#define B_WB   33792
#define B_S4   107520
#define B_WR   109568
#define SMEM_BYTES 112640

__device__ float g_agg[(size_t)N_TOT * 128];
#define EOFF 0
#define NOFF 229888
__device__ __align__(16) __half g_wh[483584];

// ---------------- helpers ----------------
__device__ __forceinline__ uint32_t smem_u32(const void* p) {
    uint32_t a;
    asm("{ .reg .u64 t; cvta.to.shared.u64 t, %1; cvt.u32.u64 %0, t; }" : "=r"(a) : "l"(p));
    return a;
}
__device__ __forceinline__ void cpa16(uint32_t s, const void* g) {
    asm volatile("cp.async.cg.shared.global [%0], [%1], 16;" :: "r"(s), "l"(g));
}
#define LDSM_X4(r0, r1, r2, r3, a) \
    asm volatile("ldmatrix.sync.aligned.m8n8.x4.shared.b16 {%0,%1,%2,%3}, [%4];" \
        : "=r"(r0), "=r"(r1), "=r"(r2), "=r"(r3) : "r"(a))
#define LDSM_X2(r0, r1, a) \
    asm volatile("ldmatrix.sync.aligned.m8n8.x2.shared.b16 {%0,%1}, [%2];" \
        : "=r"(r0), "=r"(r1) : "r"(a))
__device__ __forceinline__ void mma16(float* c, const uint32_t a[4], uint32_t b0, uint32_t b1) {
    asm volatile("mma.sync.aligned.m16n8k16.row.col.f32.f16.f16.f32 "
        "{%0,%1,%2,%3},{%4,%5,%6,%7},{%8,%9},{%0,%1,%2,%3};"
        : "+f"(c[0]), "+f"(c[1]), "+f"(c[2]), "+f"(c[3])
        : "r"(a[0]), "r"(a[1]), "r"(a[2]), "r"(a[3]), "r"(b0), "r"(b1));
}
__device__ __forceinline__ float silu_f(float v) {
    return v * __fdividef(1.f, 1.f + __expf(-v));
}

// issue tile-0 prefetch for a layer into slot 0 (slot 0 free after any GEMM: NT even)
template<int K, int WR>
__device__ __forceinline__ void prefetch0(const __half* __restrict__ Wg, int wrows,
                                          __half* Wb, int tid)
{
    for (int idx = tid; idx < WR * 8; idx += 256) {
        int n = idx >> 3, q = idx & 7;
        if (n < wrows)
            cpa16(smem_u32(Wb + n * SW_H + q * 8), Wg + (size_t)n * K + q * 8);
    }
    asm volatile("cp.async.commit_group;");
}

// GEMM: C[64, 8*NTW*4] += A[64,K](fp16 smem) @ W[wrows,K]^T  (warps 2M x 4N)
// Tile-0 prefetch assumed already issued via prefetch0.
template<int K, int WR, int NTW>
__device__ __forceinline__ void gemm16(
    const __half* __restrict__ Wg, int wrows,
    const __half* As, __half* Wb, float* c,
    int tid, int lane, int wm, int wn)
{
    constexpr int NT = K / 64;
    int mq = lane >> 3, lr = lane & 7;

    for (int kt = 0; kt < NT; kt++) {
        const __half* cur = Wb + (kt & 1) * (WR * SW_H);
        if (kt + 1 < NT) {
            __half* nxt = Wb + ((kt + 1) & 1) * (WR * SW_H);
            for (int idx = tid; idx < WR * 8; idx += 256) {
                int n = idx >> 3, q = idx & 7;
                if (n < wrows)
                    cpa16(smem_u32(nxt + n * SW_H + q * 8),
                          Wg + (size_t)n * K + (kt + 1) * 64 + q * 8);
            }
            asm volatile("cp.async.commit_group;");
            asm volatile("cp.async.wait_group 1;");
        } else {
            asm volatile("cp.async.wait_group 0;");
        }
        __syncthreads();
#pragma unroll
        for (int ks = 0; ks < 4; ks++) {
            uint32_t a0[4], a1[4];
            uint32_t aad0 = smem_u32(As + (32 * wm + (mq & 1) * 8 + lr) * SA_H
                                        + kt * 64 + ks * 16 + (mq >> 1) * 8);
            LDSM_X4(a0[0], a0[1], a0[2], a0[3], aad0);
            LDSM_X4(a1[0], a1[1], a1[2], a1[3], aad0 + 16 * SA_H * 2);
#pragma unroll
            for (int p = 0; p < NTW / 2; p++) {
                uint32_t b0, b1, b2, b3;
                uint32_t bad = smem_u32(cur + (wn * (NTW * 8) + p * 16 + (mq >> 1) * 8 + lr) * SW_H
                                            + ks * 16 + (mq & 1) * 8);
                LDSM_X4(b0, b1, b2, b3, bad);
                mma16(c + (0 * NTW + 2 * p) * 4,     a0, b0, b1);
                mma16(c + (1 * NTW + 2 * p) * 4,     a1, b0, b1);
                mma16(c + (0 * NTW + 2 * p + 1) * 4, a0, b2, b3);
                mma16(c + (1 * NTW + 2 * p + 1) * 4, a1, b2, b3);
            }
            if (NTW & 1) {
                int i = lane & 15;
                uint32_t b0, b1;
                uint32_t bad = smem_u32(cur + (wn * (NTW * 8) + (NTW - 1) * 8 + (i & 7)) * SW_H
                                            + ks * 16 + (i >> 3) * 8);
                LDSM_X2(b0, b1, bad);
                mma16(c + (0 * NTW + NTW - 1) * 4, a0, b0, b1);
                mma16(c + (1 * NTW + NTW - 1) * 4, a1, b0, b1);
            }
        }
        __syncthreads();
    }
}

// ---------------- fused MLP body (64-row tile) ----------------
template<int MODE, int WRF, int NTWF, int NVF>
__device__ __forceinline__ void mlp_body(
    int row0,
    const float* __restrict__ m, const float* __restrict__ rbf, const float* __restrict__ Wr,
    const float* __restrict__ lng, const float* __restrict__ lnb,
    const float* __restrict__ bd,
    const __half* __restrict__ Wup, const __half* __restrict__ Wd, const __half* __restrict__ Wf,
    float* __restrict__ out, int nrows, unsigned char* smraw)
{
    __half* A   = reinterpret_cast<__half*>(smraw + B_A);
    __half* Wb  = reinterpret_cast<__half*>(smraw + B_WB);
    float*  S4  = reinterpret_cast<float*>(smraw + B_S4);
    float*  WrS = reinterpret_cast<float*>(smraw + B_WR);

    int tid = threadIdx.x, wid = tid >> 5, lane = tid & 31;
    int wm = wid & 1, wn = wid >> 1, g = lane >> 2, t = lane & 3;

    // L0 tile-0 prefetch hides under stage0
    prefetch0<128, 256>(Wup, 256, Wb, tid);

    // ---- stage0: A[64, 0:128] fp16 ----
    {
        int r = tid >> 2, kh = (tid & 3) * 32;
        if (MODE == 0) {
            for (int i = tid; i < 768; i += 256) WrS[i] = Wr[i];
            __syncthreads();
            const float* rb = rbf + (size_t)(row0 + r) * 6;
            float b0 = rb[0], b1 = rb[1], b2 = rb[2], b3 = rb[3], b4 = rb[4], b5 = rb[5];
            const float* mr = m + (size_t)(row0 + r) * 128;
            for (int k0 = kh; k0 < kh + 32; k0 += 4) {
                float4 mv = *reinterpret_cast<const float4*>(mr + k0);
                float cf[4];
#pragma unroll
                for (int j = 0; j < 4; j++) {
                    const float* w = WrS + (k0 + j) * 6;
                    cf[j] = b0*w[0] + b1*w[1] + b2*w[2] + b3*w[3] + b4*w[4] + b5*w[5];
                }
                *reinterpret_cast<__half2*>(A + r * SA_H + k0)     = __floats2half2_rn(mv.x * cf[0], mv.y * cf[1]);
                *reinterpret_cast<__half2*>(A + r * SA_H + k0 + 2) = __floats2half2_rn(mv.z * cf[2], mv.w * cf[3]);
            }
        } else {
            bool valid = (row0 + r) < nrows;
            const float* srcp = g_agg + (size_t)(row0 + r) * 128;
            for (int k0 = kh; k0 < kh + 32; k0 += 4) {
                float4 v = valid ? *reinterpret_cast<const float4*>(srcp + k0)
                                 : make_float4(0.f, 0.f, 0.f, 0.f);
                *reinterpret_cast<__half2*>(A + r * SA_H + k0)     = __floats2half2_rn(v.x, v.y);
                *reinterpret_cast<__half2*>(A + r * SA_H + k0 + 2) = __floats2half2_rn(v.z, v.w);
            }
        }
    }
    __syncthreads();

    float c[64];

    // ---- L0: up (K=128) + LayerNorm ----
#pragma unroll
    for (int i = 0; i < 64; i++) c[i] = 0.f;
    gemm16<128, 256, 8>(Wup, 256, A, Wb, c, tid, lane, wm, wn);
    prefetch0<256, 256>(Wd, 256, Wb, tid);   // L1 tile-0 hides under LN epilogue
    {
        float s[4] = {0.f, 0.f, 0.f, 0.f}, q2[4] = {0.f, 0.f, 0.f, 0.f};
#pragma unroll
        for (int mt = 0; mt < 2; mt++)
#pragma unroll
            for (int nt = 0; nt < 8; nt++) {
                const float* cc = c + (mt * 8 + nt) * 4;
                s[mt*2]   += cc[0] + cc[1]; q2[mt*2]   += cc[0]*cc[0] + cc[1]*cc[1];
                s[mt*2+1] += cc[2] + cc[3]; q2[mt*2+1] += cc[2]*cc[2] + cc[3]*cc[3];
            }
#pragma unroll
        for (int off = 1; off <= 2; off <<= 1)
#pragma unroll
            for (int i = 0; i < 4; i++) {
                s[i]  += __shfl_xor_sync(0xffffffffu, s[i],  off);
                q2[i] += __shfl_xor_sync(0xffffffffu, q2[i], off);
            }
        if (t == 0) {
#pragma unroll
            for (int i = 0; i < 4; i++) {
                int row = 32 * wm + 16 * (i >> 1) + g + 8 * (i & 1);
                S4[row * 8 + wn]     = s[i];
                S4[row * 8 + 4 + wn] = q2[i];
            }
        }
        __syncthreads();
        float mu[4], rs[4];
#pragma unroll
        for (int i = 0; i < 4; i++) {
            int row = 32 * wm + 16 * (i >> 1) + g + 8 * (i & 1);
            float sum = S4[row*8+0] + S4[row*8+1] + S4[row*8+2] + S4[row*8+3];
            float sq  = S4[row*8+4] + S4[row*8+5] + S4[row*8+6] + S4[row*8+7];
            float m_ = sum * (1.f / 256.f);
            mu[i] = m_;
            rs[i] = rsqrtf(sq * (1.f / 256.f) - m_ * m_ + 1e-5f);
        }
#pragma unroll
        for (int mt = 0; mt < 2; mt++) {
            int rA = 32 * wm + 16 * mt + g, rB = rA + 8;
            int iA = mt * 2, iB = mt * 2 + 1;
#pragma unroll
            for (int nt = 0; nt < 8; nt++) {
                int col = 64 * wn + 8 * nt + 2 * t;
                const float* cc = c + (mt * 8 + nt) * 4;
                float g0 = __ldg(lng + col), g1 = __ldg(lng + col + 1);
                float e0 = __ldg(lnb + col), e1 = __ldg(lnb + col + 1);
                *reinterpret_cast<__half2*>(A + rA * SA_H + col) =
                    __floats2half2_rn((cc[0] - mu[iA]) * rs[iA] * g0 + e0,
                                      (cc[1] - mu[iA]) * rs[iA] * g1 + e1);
                *reinterpret_cast<__half2*>(A + rB * SA_H + col) =
                    __floats2half2_rn((cc[2] - mu[iB]) * rs[iB] * g0 + e0,
                                      (cc[3] - mu[iB]) * rs[iB] * g1 + e1);
            }
        }
    }

    // ---- L1..L3 dense + SiLU ----
    for (int L = 0; L < 3; L++) {
#pragma unroll
        for (int i = 0; i < 64; i++) c[i] = 0.f;
        gemm16<256, 256, 8>(Wd + L * 65536, 256, A, Wb, c, tid, lane, wm, wn);
        // hoist next layer's tile-0 under this epilogue
        if (L < 2) {
            prefetch0<256, 256>(Wd + (L + 1) * 65536, 256, Wb, tid);
        } else {
            if (MODE == 0) prefetch0<256, 8>(Wf, NVF, Wb, tid);
            else           prefetch0<256, 96>(Wf, NVF, Wb, tid);
        }
        const float* bias = bd + L * 256;
#pragma unroll
        for (int mt = 0; mt < 2; mt++) {
            int rA = 32 * wm + 16 * mt + g, rB = rA + 8;
#pragma unroll
            for (int nt = 0; nt < 8; nt++) {
                int col = 64 * wn + 8 * nt + 2 * t;
                const float* cc = c + (mt * 8 + nt) * 4;
                float b0 = __ldg(bias + col), b1 = __ldg(bias + col + 1);
                *reinterpret_cast<__half2*>(A + rA * SA_H + col) =
                    __floats2half2_rn(silu_f(cc[0] + b0), silu_f(cc[1] + b1));
                *reinterpret_cast<__half2*>(A + rB * SA_H + col) =
                    __floats2half2_rn(silu_f(cc[2] + b0), silu_f(cc[3] + b1));
            }
        }
        __syncthreads();
    }

    // ---- final projection (tensor GEMM both modes; garbage pad cols never stored) ----
#pragma unroll
    for (int i = 0; i < 2 * NTWF * 4; i++) c[i] = 0.f;
    gemm16<256, WRF, NTWF>(Wf, NVF, A, Wb, c, tid, lane, wm, wn);

    if (MODE == 0) {
        if (wn == 0 && t == 0) {
#pragma unroll
            for (int mt = 0; mt < 2; mt++) {
                int rA = row0 + 32 * wm + 16 * mt + g, rB = rA + 8;
                out[(size_t)rA * 2 + 0] = c[mt * NTWF * 4 + 0];
                out[(size_t)rA * 2 + 1] = c[mt * NTWF * 4 + 1];
                out[(size_t)rB * 2 + 0] = c[mt * NTWF * 4 + 2];
                out[(size_t)rB * 2 + 1] = c[mt * NTWF * 4 + 3];
            }
        }
    } else {
#pragma unroll
        for (int mt = 0; mt < 2; mt++) {
            int rA = row0 + 32 * wm + 16 * mt + g, rB = rA + 8;
#pragma unroll
            for (int nt = 0; nt < NTWF; nt++) {
                int col = wn * (NTWF * 8) + nt * 8 + 2 * t;
                const float* cc = c + (mt * NTWF + nt) * 4;
                if (rA < nrows) {
                    if (col < 95)     out[(size_t)rA * 95 + col]     = cc[0];
                    if (col + 1 < 95) out[(size_t)rA * 95 + col + 1] = cc[1];
                }
                if (rB < nrows) {
                    if (col < 95)     out[(size_t)rB * 95 + col]     = cc[2];
                    if (col + 1 < 95) out[(size_t)rB * 95 + col + 1] = cc[3];
                }
            }
        }
    }
}

// ---------------- one fused launch: edge blocks then node blocks ----------------
__global__ void __launch_bounds__(256, 2) fused_all(
    const float* __restrict__ m, const float* __restrict__ rbf, const float* __restrict__ Wr_e,
    const float* __restrict__ lng_e, const float* __restrict__ lnb_e, const float* __restrict__ bd_e,
    const float* __restrict__ lng_n, const float* __restrict__ lnb_n, const float* __restrict__ bd_n,
    float* __restrict__ edge_out, float* __restrict__ node_out)
{
    extern __shared__ unsigned char smraw[];
    if (blockIdx.x < EB) {
        mlp_body<0, 8, 1, 2>(blockIdx.x * 64, m, rbf, Wr_e, lng_e, lnb_e, bd_e,
                             g_wh + EOFF, g_wh + EOFF + 32768, g_wh + EOFF + 229376,
                             edge_out, E_TOT, smraw);
    } else {
        mlp_body<1, 96, 3, 95>((blockIdx.x - EB) * 64, nullptr, nullptr, nullptr,
                               lng_n, lnb_n, bd_n,
                               g_wh + NOFF, g_wh + NOFF + 32768, g_wh + NOFF + 229376,
                               node_out, N_TOT, smraw);
    }
}

// ---------------- prep kernels ----------------
__global__ void cvt_branch(const float* __restrict__ up, const float* __restrict__ wd,
                           const float* __restrict__ fin, int fin_n, int base)
{
    int i = blockIdx.x * 256 + threadIdx.x;
    if (i < 32768)                 g_wh[base + i] = __float2half_rn(up[i]);
    else if (i < 229376)           g_wh[base + i] = __float2half_rn(wd[i - 32768]);
    else if (i < 229376 + fin_n)   g_wh[base + i] = __float2half_rn(fin[i - 229376]);
}

__global__ void zero_agg_kernel(int base)
{
    size_t n = (size_t)N_TOT * 64;
    for (size_t i = (size_t)blockIdx.x * blockDim.x + threadIdx.x; i < n;
         i += (size_t)gridDim.x * blockDim.x)
        g_agg[base + i] = 0.f;
}

// ---------------- scatter: proven scalar-atomic version (R4/R5) ----------------
__global__ void __launch_bounds__(256) scatter_kernel(
    const float* __restrict__ m, const float* __restrict__ rbf,
    const int* __restrict__ src, const float* __restrict__ Wr)
{
    __shared__ float Wrs[128 * 6];
    for (int idx = threadIdx.x; idx < 128 * 6; idx += 256) Wrs[idx] = Wr[idx];
    __syncthreads();
    int sub = threadIdx.x >> 7;
    int k   = threadIdx.x & 127;
    for (long long e = (long long)blockIdx.x * 2 + sub; e < E_TOT;
         e += (long long)gridDim.x * 2) {
        const float* rb = rbf + e * 6;
        float r0 = __ldg(rb+0), r1 = __ldg(rb+1), r2 = __ldg(rb+2);
        float r3 = __ldg(rb+3), r4 = __ldg(rb+4), r5 = __ldg(rb+5);
        const float* wr = Wrs + k * 6;
        float cc = r0*wr[0] + r1*wr[1] + r2*wr[2] + r3*wr[3] + r4*wr[4] + r5*wr[5];
        float v = m[(size_t)e * 128 + k] * cc;
        int s = __ldg(src + e);
        atomicAdd(g_agg + (size_t)s * 128 + k, v);
    }
}

// ---------------- launch ----------------
extern "C" void kernel_launch(void* const* d_in, const int* in_sizes, int n_in,
                              void* d_out, int out_size)
{
    const float* m       = (const float*)d_in[0];
    const float* rbf     = (const float*)d_in[1];
    const int*   src     = (const int*)  d_in[2];
    const float* W_rbf_e = (const float*)d_in[3];
    const float* W_up_e  = (const float*)d_in[4];
    const float* ln_g_e  = (const float*)d_in[5];
    const float* ln_b_e  = (const float*)d_in[6];
    const float* Wd_e    = (const float*)d_in[7];
    const float* bd_e    = (const float*)d_in[8];
    const float* W_fin_e = (const float*)d_in[9];
    const float* W_rbf_n = (const float*)d_in[10];
    const float* W_up_n  = (const float*)d_in[11];
    const float* ln_g_n  = (const float*)d_in[12];
    const float* ln_b_n  = (const float*)d_in[13];
    const float* Wd_n    = (const float*)d_in[14];
    const float* bd_n    = (const float*)d_in[15];
    const float* W_fin_n = (const float*)d_in[16];

    float* edge_out = (float*)d_out;
    float* node_out = (float*)d_out + (size_t)E_TOT * 2;

    cudaFuncSetAttribute((const void*)fused_all,
                         cudaFuncAttributeMaxDynamicSharedMemorySize, SMEM_BYTES);

    cvt_branch<<<(229888 + 255) / 256, 256>>>(W_up_e, Wd_e, W_fin_e, 512,   EOFF);
    cvt_branch<<<(253696 + 255) / 256, 256>>>(W_up_n, Wd_n, W_fin_n, 24320, NOFF);
    zero_agg_kernel<<<256, 256>>>(0);
    zero_agg_kernel<<<256, 256>>>(N_TOT * 64);
    scatter_kernel<<<1184, 256>>>(m, rbf, src, W_rbf_n);
    fused_all<<<EB + NB, 256, SMEM_BYTES>>>(
        m, rbf, W_rbf_e, ln_g_e, ln_b_e, bd_e, ln_g_n, ln_b_n, bd_n,
        edge_out, node_out);
}